// round 4
// baseline (speedup 1.0000x reference)
#include <cuda_runtime.h>
#include <math.h>

typedef unsigned long long ull;

#define Bn  64
#define Tn  128
#define En  300
#define Hn  256
#define G2  512

#define WIH_S 304     // padded stride for K=300 rows (16B-aligned pairs)
#define WHH_S 260
#define H_S   260

// ---------------- device scratch ----------------
__device__ float g_hbuf[2][2][Bn*Hn];            // [dir][parity][b*256 + u]
__device__ float g_pooled[Bn*G2];
__device__ float g_act0[Bn*G2];
__device__ float g_act1[Bn*G2];
__device__ unsigned g_cnt[2];

// ---------------- packed f32x2 helpers ----------------
__device__ __forceinline__ void fma2(ull& d, ull a, ull b){
    asm("fma.rn.f32x2 %0, %1, %2, %0;" : "+l"(d) : "l"(a), "l"(b));
}
__device__ __forceinline__ float hadd2(ull v){
    float a, b;
    asm("mov.b64 {%0, %1}, %2;" : "=f"(a), "=f"(b) : "l"(v));
    return a + b;
}
__device__ __forceinline__ void ldsv2(ull& a, ull& b, unsigned addr){
    asm volatile("ld.shared.v2.b64 {%0, %1}, [%2];" : "=l"(a), "=l"(b) : "r"(addr));
}

// ---------------- kernel 0: barrier reset ----------------
__global__ void reset_kernel(){
    if (threadIdx.x < 2) g_cnt[threadIdx.x] = 0u;
}

// ---------------- fused kernel: emb-gather + x-proj + BiLSTM + pooled sum ----------------
// 128 blocks = dir(2) x bq(4) x ubk(16). 256 threads = bl(16) x ul(16).
// Thread (bl,ul) owns batch b=bq*16+bl, unit u=ubk*16+ul: 4 gate dots per step,
// each = w_ih[300]·x (computed fresh each step from staged emb row) + w_hh[256]·h.
// x-GEMM has no h dependency -> hides barrier wait, emb prefetch, h copy.
__global__ void __launch_bounds__(256,1) fused_kernel(
    const int* __restrict__ sentence, const float* __restrict__ emb,
    const float* __restrict__ wihf, const float* __restrict__ whhf,
    const float* __restrict__ bihf, const float* __restrict__ bhhf,
    const float* __restrict__ wihb, const float* __restrict__ whhb,
    const float* __restrict__ bihb, const float* __restrict__ bhhb,
    const int* __restrict__ text_len)
{
    extern __shared__ __align__(16) float dyn[];
    float* h_sm   = dyn;                  // 16*260   = 4160
    float* whh_s  = dyn + 4160;           // 64*260   = 16640
    float* wih_s  = dyn + 20800;          // 64*304   = 19456
    float* x_sm0  = dyn + 40256;          // 16*304   = 4864
    float* x_sm1  = dyn + 45120;          // 16*304   = 4864
    int*   tok_s  = (int*)(dyn + 49984);  // 16*128 ints = 8192 B

    int bx  = blockIdx.x;
    int dir = bx >> 6;
    int rr  = bx & 63;
    int bq  = rr >> 4;
    int ubk = rr & 15;
    int tid = threadIdx.x;
    int bl = tid & 15, ul = tid >> 4;
    int b = bq*16 + bl;
    int u = ubk*16 + ul;

    const float* wih = dir ? wihb : wihf;
    const float* whh = dir ? whhb : whhf;
    const float* bih = dir ? bihb : bihf;
    const float* bhh = dir ? bhhb : bhhf;

    // ---- one-time staging ----
    for (int i = tid; i < 16*Tn; i += 256)
        tok_s[i] = sentence[(bq*16 + (i >> 7))*Tn + (i & 127)];
    #pragma unroll 4
    for (int row = 0; row < 64; ++row) {
        int ul2 = row >> 2, g = row & 3;
        whh_s[row*WHH_S + tid] = whh[(size_t)(g*Hn + ubk*16 + ul2) * Hn + tid];
    }
    for (int i = tid; i < 64*En; i += 256) {
        int row = i / En, k = i - row*En;
        int ul2 = row >> 2, g = row & 3;
        wih_s[row*WIH_S + k] = wih[(size_t)(g*Hn + ubk*16 + ul2) * En + k];
    }
    float bsum0, bsum1, bsum2, bsum3;
    bsum0 = bih[0*Hn + u] + bhh[0*Hn + u];
    bsum1 = bih[1*Hn + u] + bhh[1*Hn + u];
    bsum2 = bih[2*Hn + u] + bhh[2*Hn + u];
    bsum3 = bih[3*Hn + u] + bhh[3*Hn + u];

    // ---- prologue: stage emb rows for the first timestep into buf0 ----
    {
        int tpos0 = dir ? (Tn - 1) : 0;
        for (int i = tid; i < 16*75; i += 256) {
            int r = i / 75, cc = i - r*75;
            float4 v = *(const float4*)(emb + (size_t)tok_s[r*Tn + tpos0]*En + cc*4);
            *(float4*)&x_sm0[r*WIH_S + cc*4] = v;
        }
    }
    __syncthreads();

    unsigned hb_addr  = (unsigned)__cvta_generic_to_shared(h_sm  + bl*H_S);
    unsigned wbh_addr = (unsigned)__cvta_generic_to_shared(whh_s + (ul*4)*WHH_S);
    unsigned wbx_addr = (unsigned)__cvta_generic_to_shared(wih_s + (ul*4)*WIH_S);
    unsigned xb0 = (unsigned)__cvta_generic_to_shared(x_sm0 + bl*WIH_S);
    unsigned xb1 = (unsigned)__cvta_generic_to_shared(x_sm1 + bl*WIH_S);

    float c_state = 0.f, pooled = 0.f;
    int len = text_len[b];
    unsigned* cnt = &g_cnt[dir];

    for (int step = 0; step < Tn; ++step) {
        int tpos = dir ? (Tn - 1 - step) : step;
        unsigned xb = (step & 1) ? xb1 : xb0;
        float* xnxt = (step & 1) ? x_sm0 : x_sm1;

        // ---- issue prefetch LDGs for next timestep's emb rows (hidden by x-GEMM) ----
        float4 pf[5];
        int havepf = (step < Tn - 1);
        if (havepf) {
            int tnext = dir ? (Tn - 2 - step) : (step + 1);
            #pragma unroll
            for (int q = 0; q < 5; q++) {
                int i = tid + q*256;
                if (i < 1200) {
                    int r = i / 75, cc = i - r*75;
                    pf[q] = *(const float4*)(emb + (size_t)tok_s[r*Tn + tnext]*En + cc*4);
                }
            }
        }

        // ---- x-projection gates (no h dependency) ----
        ull a0=0,a1=0,a2=0,a3=0,e0=0,e1=0,e2=0,e3=0;
        #pragma unroll 5
        for (int k0 = 0; k0 < En; k0 += 4) {
            ull x01, x23, w01, w23;
            ldsv2(x01, x23, xb + k0*4);
            ldsv2(w01, w23, wbx_addr + k0*4);          fma2(a0,w01,x01); fma2(e0,w23,x23);
            ldsv2(w01, w23, wbx_addr + 1216 + k0*4);   fma2(a1,w01,x01); fma2(e1,w23,x23);
            ldsv2(w01, w23, wbx_addr + 2432 + k0*4);   fma2(a2,w01,x01); fma2(e2,w23,x23);
            ldsv2(w01, w23, wbx_addr + 3648 + k0*4);   fma2(a3,w01,x01); fma2(e3,w23,x23);
        }
        float g0 = bsum0 + hadd2(a0) + hadd2(e0);
        float g1 = bsum1 + hadd2(a1) + hadd2(e1);
        float g2 = bsum2 + hadd2(a2) + hadd2(e2);
        float g3 = bsum3 + hadd2(a3) + hadd2(e3);

        // ---- commit prefetched emb rows to the other buffer ----
        if (havepf) {
            #pragma unroll
            for (int q = 0; q < 5; q++) {
                int i = tid + q*256;
                if (i < 1200) {
                    int r = i / 75, cc = i - r*75;
                    *(float4*)&xnxt[r*WIH_S + cc*4] = pf[q];
                }
            }
        }

        if (step > 0) {
            // ---- per-dir grid barrier wait (arrive happened at end of prev step) ----
            if (tid == 0) {
                unsigned tgt = 64u * (unsigned)step;
                unsigned v;
                do {
                    asm volatile("ld.acquire.gpu.global.u32 %0, [%1];"
                                 : "=r"(v) : "l"(cnt) : "memory");
                } while (v < tgt);
            }
            __syncthreads();
            // ---- copy this block's batch-quarter of h(t-1) into smem ----
            const float* hsrc = g_hbuf[dir][(step + 1) & 1] + (size_t)bq*16*Hn;
            #pragma unroll
            for (int j = 0; j < 4; j++) {
                int idx = tid + j*256;
                int row = idx >> 6, c4 = idx & 63;
                float4 v = __ldcg((const float4*)(hsrc + row*Hn + c4*4));
                *(float4*)&h_sm[row*H_S + c4*4] = v;
            }
            __syncthreads();
            // ---- h-recurrence gate dots ----
            ull h0=0,h1=0,h2=0,h3=0,f0=0,f1=0,f2=0,f3=0;
            #pragma unroll 4
            for (int k0 = 0; k0 < Hn; k0 += 4) {
                ull hh01, hh23, w01, w23;
                ldsv2(hh01, hh23, hb_addr + k0*4);
                ldsv2(w01, w23, wbh_addr + k0*4);          fma2(h0,w01,hh01); fma2(f0,w23,hh23);
                ldsv2(w01, w23, wbh_addr + 1040 + k0*4);   fma2(h1,w01,hh01); fma2(f1,w23,hh23);
                ldsv2(w01, w23, wbh_addr + 2080 + k0*4);   fma2(h2,w01,hh01); fma2(f2,w23,hh23);
                ldsv2(w01, w23, wbh_addr + 3120 + k0*4);   fma2(h3,w01,hh01); fma2(f3,w23,hh23);
            }
            g0 += hadd2(h0) + hadd2(f0);
            g1 += hadd2(h1) + hadd2(f1);
            g2 += hadd2(h2) + hadd2(f2);
            g3 += hadd2(h3) + hadd2(f3);
        }

        float ig = 1.f / (1.f + __expf(-g0));
        float fg = 1.f / (1.f + __expf(-g1));
        float gg = tanhf(g2);
        float og = 1.f / (1.f + __expf(-g3));
        c_state = fg * c_state + ig * gg;
        float h = og * tanhf(c_state);

        g_hbuf[dir][step & 1][b*Hn + u] = h;
        if (tpos < len) pooled += h;

        __syncthreads();                      // drain h stores + xnxt STS
        if (tid == 0)
            asm volatile("red.release.gpu.global.add.u32 [%0], 1;"
                         :: "l"(cnt) : "memory");
    }
    g_pooled[b*G2 + dir*Hn + u] = pooled;
}

// ---------------- FC layer GEMM (unchanged from R3) ----------------
__global__ void __launch_bounds__(256,1) fc_kernel(
    const float* __restrict__ X, const float* __restrict__ W,
    const float* __restrict__ bias, const int* __restrict__ lenp,
    float* __restrict__ out, int K, int kshift, int N, int dorelu)
{
    extern __shared__ __align__(16) float fsm[];
    int KP = K + 2;
    float* Xs = fsm;
    float* Ws = fsm + 64*KP;
    int tid = threadIdx.x;
    int jt = blockIdx.x;

    for (int i = tid; i < 64*K; i += 256) {
        int b = i >> kshift, k = i & (K-1);
        Xs[b*KP + k] = X[i];
    }
    for (int i = tid; i < 16*K; i += 256) {
        int jl = i >> kshift, k = i & (K-1);
        int j = jt*16 + jl;
        Ws[jl*KP + k] = (j < N) ? W[(size_t)j*K + k] : 0.f;
    }
    __syncthreads();

    int bl = tid & 15, jl = tid >> 4;
    int j = jt*16 + jl;
    if (j >= N) return;

    ull acc[4];
    #pragma unroll
    for (int q = 0; q < 4; q++) acc[q] = 0ull;
    const float* wrow = &Ws[jl*KP];
    #pragma unroll 4
    for (int k = 0; k < K; k += 2) {
        ull wp = *(const ull*)(wrow + k);
        #pragma unroll
        for (int q = 0; q < 4; q++) {
            ull xpr = *(const ull*)(&Xs[(bl + 16*q)*KP + k]);
            fma2(acc[q], xpr, wp);
        }
    }
    #pragma unroll
    for (int q = 0; q < 4; q++) {
        int b = bl + 16*q;
        float bscale = lenp ? (float)lenp[b] : 1.f;
        float v = hadd2(acc[q]) + bias[j] * bscale;
        if (dorelu) v = fmaxf(v, 0.f);
        out[b*N + j] = v;
    }
}

// ---------------- host entry ----------------
extern "C" void kernel_launch(void* const* d_in, const int* in_sizes, int n_in,
                              void* d_out, int out_size)
{
    const int*   sentence = (const int*)d_in[0];
    const int*   text_len = (const int*)d_in[4];
    const float* emb  = (const float*)d_in[10];
    const float* wihf = (const float*)d_in[11];
    const float* whhf = (const float*)d_in[12];
    const float* bihf = (const float*)d_in[13];
    const float* bhhf = (const float*)d_in[14];
    const float* wihb = (const float*)d_in[15];
    const float* whhb = (const float*)d_in[16];
    const float* bihb = (const float*)d_in[17];
    const float* bhhb = (const float*)d_in[18];
    const float* gatw = (const float*)d_in[19];
    const float* gatb = (const float*)d_in[20];
    const float* fc1w = (const float*)d_in[21];
    const float* fc1b = (const float*)d_in[22];
    const float* fc2w = (const float*)d_in[23];
    const float* fc2b = (const float*)d_in[24];
    const float* fcfw = (const float*)d_in[25];
    const float* fcfb = (const float*)d_in[26];
    float* out = (float*)d_out;

    const int fused_smem = 49984*4 + 16*Tn*4;   // 208,128 B
    cudaFuncSetAttribute(fused_kernel, cudaFuncAttributeMaxDynamicSharedMemorySize, fused_smem);
    const int fc_smem512 = 80 * 514 * 4;
    const int fc_smem256 = 80 * 258 * 4;
    cudaFuncSetAttribute(fc_kernel, cudaFuncAttributeMaxDynamicSharedMemorySize, fc_smem512);

    void *p_pooled, *p_a0, *p_a1;
    cudaGetSymbolAddress(&p_pooled, g_pooled);
    cudaGetSymbolAddress(&p_a0, g_act0);
    cudaGetSymbolAddress(&p_a1, g_act1);

    reset_kernel<<<1, 32>>>();
    fused_kernel<<<128, 256, fused_smem>>>(sentence, emb,
                                           wihf, whhf, bihf, bhhf,
                                           wihb, whhb, bihb, bhhb, text_len);
    fc_kernel<<<32, 256, fc_smem512>>>((const float*)p_pooled, gatw, gatb, text_len,
                                       (float*)p_a0, 512, 9, 512, 1);
    fc_kernel<<<16, 256, fc_smem512>>>((const float*)p_a0, fc1w, fc1b, nullptr,
                                       (float*)p_a1, 512, 9, 256, 1);
    fc_kernel<<<16, 256, fc_smem256>>>((const float*)p_a1, fc2w, fc2b, nullptr,
                                       (float*)p_a0, 256, 8, 256, 1);
    fc_kernel<<<1, 256, fc_smem256>>> ((const float*)p_a0, fcfw, fcfb, nullptr,
                                       out, 256, 8, 2, 0);
}